// round 10
// baseline (speedup 1.0000x reference)
#include <cuda_runtime.h>
#include <cuda_bf16.h>
#include <cuda_fp16.h>
#include <cstdint>

#define N_NODES 100000
#define N_EDGES 1600000
// dims: IN=128, HIDDEN=128, OUT=64

#define SCAN_B 1024
#define SCAN_G ((N_NODES + SCAN_B - 1) / SCAN_B)   // 98

// ---------------- scratch (device globals: allocation-free) ----------------
__device__ int    g_cnt[N_NODES];
__device__ int    g_off[N_NODES];
__device__ int    g_pos[N_NODES];
__device__ float  g_inv[N_NODES];
__device__ unsigned long long g_lk[SCAN_G];   // decoupled-lookback state
__device__ int    g_csr[N_EDGES];
__device__ __half g_hn [N_NODES * 128];   // F' = feat @ W1            (fp16)
__device__ __half g_h1 [N_NODES * 128];   // relu((agg+self)*inv + b1) (fp16)
__device__ __half g_y2 [N_NODES * 64];    // h1 @ W2                   (fp16)
__device__ __nv_bfloat16 g_W1h[128 * 128];
__device__ __nv_bfloat16 g_W1l[128 * 128];
__device__ __nv_bfloat16 g_W2h[128 * 64];
__device__ __nv_bfloat16 g_W2l[128 * 64];

// ---------------- init: zero counts + lookback state + split weights -------
__global__ void k_init(const float* __restrict__ W1,
                       const float* __restrict__ W2,
                       __nv_bfloat16* __restrict__ W1h,
                       __nv_bfloat16* __restrict__ W1l,
                       __nv_bfloat16* __restrict__ W2h,
                       __nv_bfloat16* __restrict__ W2l) {
    int i = blockIdx.x * blockDim.x + threadIdx.x;
    if (i < N_NODES) g_cnt[i] = 0;
    if (i < SCAN_G)  g_lk[i] = 0ull;
    if (i < 128 * 128) {
        float w = W1[i];
        __nv_bfloat16 h = __float2bfloat16(w);
        W1h[i] = h;
        W1l[i] = __float2bfloat16(w - __bfloat162float(h));
    }
    if (i < 128 * 64) {
        float w = W2[i];
        __nv_bfloat16 h = __float2bfloat16(w);
        W2h[i] = h;
        W2l[i] = __float2bfloat16(w - __bfloat162float(h));
    }
}

// ---------------- histogram (4 edges per thread, int4 loads) ----------------
__global__ void k_hist(const int4* __restrict__ dst4) {
    int t = blockIdx.x * blockDim.x + threadIdx.x;
    if (t < N_EDGES / 4) {
        int4 d = dst4[t];
        atomicAdd(&g_cnt[d.x], 1);
        atomicAdd(&g_cnt[d.y], 1);
        atomicAdd(&g_cnt[d.z], 1);
        atomicAdd(&g_cnt[d.w], 1);
    }
}

// ---------------- single-pass scan (decoupled lookback) --------------------
// 98 blocks, all resident simultaneously (98 < 148 SMs) -> spin-wait is safe.
__global__ void __launch_bounds__(SCAN_B)
k_scan() {
    __shared__ int sw[32];
    __shared__ int s_pref;
    const int t = threadIdx.x;
    const int b = blockIdx.x;
    const int i = b * SCAN_B + t;

    int v = (i < N_NODES) ? g_cnt[i] : 0;

    // warp-level inclusive scan
    int incl = v;
#pragma unroll
    for (int o = 1; o < 32; o <<= 1) {
        int y = __shfl_up_sync(0xffffffffu, incl, o);
        if ((t & 31) >= o) incl += y;
    }
    if ((t & 31) == 31) sw[t >> 5] = incl;
    __syncthreads();

    if (t < 32) {
        // scan of warp sums + block aggregate
        int x = sw[t];
        int xi = x;
#pragma unroll
        for (int o = 1; o < 32; o <<= 1) {
            int y = __shfl_up_sync(0xffffffffu, xi, o);
            if (t >= o) xi += y;
        }
        sw[t] = xi - x;                                   // exclusive warp offsets
        int total = __shfl_sync(0xffffffffu, xi, 31);     // block aggregate

        int pref = 0;
        if (b > 0) {
            // publish aggregate (flag=1)
            if (t == 0)
                atomicExch(&g_lk[b], (1ull << 32) | (unsigned)total);
            // warp-parallel lookback
            int j = b - 1;
            while (true) {
                int jj = j - t;
                unsigned long long u;
                if (jj >= 0) {
                    do { u = *(volatile unsigned long long*)&g_lk[jj]; }
                    while ((u >> 32) == 0ull);
                } else {
                    u = (2ull << 32);   // virtual inclusive 0 below index 0
                }
                int flag = (int)(u >> 32);
                int val  = (int)(u & 0xffffffffu);
                unsigned mask = __ballot_sync(0xffffffffu, flag == 2);
                int k = __ffs(mask) - 1;   // smallest lane = largest index with inclusive
                int contrib;
                if (mask) contrib = (t <= k) ? val : 0;
                else      contrib = val;   // full window of aggregates
#pragma unroll
                for (int o = 16; o > 0; o >>= 1)
                    contrib += __shfl_down_sync(0xffffffffu, contrib, o);
                contrib = __shfl_sync(0xffffffffu, contrib, 0);
                pref += contrib;
                if (mask) break;
                j -= 32;
            }
        }
        if (t == 0) {
            atomicExch(&g_lk[b], (2ull << 32) | (unsigned)(pref + total));
            s_pref = pref;
        }
    }
    __syncthreads();

    if (i < N_NODES) {
        int excl = incl - v + sw[t >> 5] + s_pref;
        g_off[i] = excl;
        g_pos[i] = excl;
        g_inv[i] = 1.0f / (float)(v + 1);
    }
}

// ---------------- CSR fill (4 edges per thread, int4 loads) ----------------
__global__ void k_fill(const int4* __restrict__ src4, const int4* __restrict__ dst4) {
    cudaTriggerProgrammaticLaunchCompletion();   // let agg128 prologue launch
    int t = blockIdx.x * blockDim.x + threadIdx.x;
    if (t < N_EDGES / 4) {
        int4 s = src4[t];
        int4 d = dst4[t];
        g_csr[atomicAdd(&g_pos[d.x], 1)] = s.x;
        g_csr[atomicAdd(&g_pos[d.y], 1)] = s.y;
        g_csr[atomicAdd(&g_pos[d.z], 1)] = s.z;
        g_csr[atomicAdd(&g_pos[d.w], 1)] = s.w;
    }
}

// ---------------- agg128 (fp16 in/out): h1 = relu((agg(F')+F')*inv + b1) ---
// PDL consumer (of k_fill) + producer (for gemm2)
__global__ void __launch_bounds__(256)
k_agg128h(const uint2* __restrict__ x, const float* __restrict__ bias,
          uint2* __restrict__ out) {
    const int warp = (blockIdx.x * blockDim.x + threadIdx.x) >> 5;
    const int lane = threadIdx.x & 31;
    if (warp >= N_NODES) return;

    // prologue: everything not depending on g_csr (off/cnt/inv from k_scan,
    // self row from GEMM1 — both full stream dependencies)
    const int start = g_off[warp];
    const int cnt   = g_cnt[warp];
    const float inv = g_inv[warp];
    float4 bb = ((const float4*)bias)[lane];

    float4 acc;
    {
        uint2 raw = x[(size_t)warp * 32 + lane];   // self term
        float2 a = __half22float2(*(const __half2*)&raw.x);
        float2 b = __half22float2(*(const __half2*)&raw.y);
        acc = make_float4(a.x, a.y, b.x, b.y);
    }

    cudaGridDependencySynchronize();               // wait: g_csr complete
    cudaTriggerProgrammaticLaunchCompletion();     // let gemm2 prologue launch

    for (int i0 = 0; i0 < cnt; i0 += 32) {
        const int nb = min(32, cnt - i0);
        int idx = 0;
        if (lane < nb) idx = g_csr[start + i0 + lane];

        int j = 0;
        for (; j + 8 <= nb; j += 8) {
            int s[8];
#pragma unroll
            for (int k = 0; k < 8; k++) s[k] = __shfl_sync(0xffffffffu, idx, j + k);
            uint2 v[8];
#pragma unroll
            for (int k = 0; k < 8; k++) v[k] = x[(size_t)s[k] * 32 + lane];
#pragma unroll
            for (int k = 0; k < 8; k++) {
                float2 a = __half22float2(*(const __half2*)&v[k].x);
                float2 b = __half22float2(*(const __half2*)&v[k].y);
                acc.x += a.x; acc.y += a.y; acc.z += b.x; acc.w += b.y;
            }
        }
        for (; j < nb; j++) {
            int s = __shfl_sync(0xffffffffu, idx, j);
            uint2 v = x[(size_t)s * 32 + lane];
            float2 a = __half22float2(*(const __half2*)&v.x);
            float2 b = __half22float2(*(const __half2*)&v.y);
            acc.x += a.x; acc.y += a.y; acc.z += b.x; acc.w += b.y;
        }
    }

    acc.x = fmaxf(acc.x * inv + bb.x, 0.f);
    acc.y = fmaxf(acc.y * inv + bb.y, 0.f);
    acc.z = fmaxf(acc.z * inv + bb.z, 0.f);
    acc.w = fmaxf(acc.w * inv + bb.w, 0.f);
    uint2 o;
    *(__half2*)&o.x = __floats2half2_rn(acc.x, acc.y);
    *(__half2*)&o.y = __floats2half2_rn(acc.z, acc.w);
    __stcs(&out[(size_t)warp * 32 + lane], o);
}

// ---------------- agg64 (fp16 in, fp32 out): out = (agg(y2)+y2)*inv + b2 ---
// PDL consumer (of gemm2)
__global__ void __launch_bounds__(256)
k_agg64h(const uint32_t* __restrict__ x, const float* __restrict__ bias,
         float2* __restrict__ out) {
    const int warp = (blockIdx.x * blockDim.x + threadIdx.x) >> 5;
    const int lane = threadIdx.x & 31;
    if (warp >= N_NODES) return;

    // prologue: CSR metadata + bias (independent of y2)
    const int start = g_off[warp];
    const int cnt   = g_cnt[warp];
    const float inv = g_inv[warp];
    float2 bb = ((const float2*)bias)[lane];

    cudaGridDependencySynchronize();   // wait: y2 complete

    float2 acc;
    {
        uint32_t raw = x[(size_t)warp * 32 + lane];   // self term
        acc = __half22float2(*(const __half2*)&raw);
    }

    for (int i0 = 0; i0 < cnt; i0 += 32) {
        const int nb = min(32, cnt - i0);
        int idx = 0;
        if (lane < nb) idx = g_csr[start + i0 + lane];

        int j = 0;
        for (; j + 8 <= nb; j += 8) {
            int s[8];
#pragma unroll
            for (int k = 0; k < 8; k++) s[k] = __shfl_sync(0xffffffffu, idx, j + k);
            uint32_t v[8];
#pragma unroll
            for (int k = 0; k < 8; k++) v[k] = x[(size_t)s[k] * 32 + lane];
#pragma unroll
            for (int k = 0; k < 8; k++) {
                float2 f = __half22float2(*(const __half2*)&v[k]);
                acc.x += f.x; acc.y += f.y;
            }
        }
        for (; j < nb; j++) {
            int s = __shfl_sync(0xffffffffu, idx, j);
            uint32_t v = x[(size_t)s * 32 + lane];
            float2 f = __half22float2(*(const __half2*)&v);
            acc.x += f.x; acc.y += f.y;
        }
    }

    acc.x = acc.x * inv + bb.x;
    acc.y = acc.y * inv + bb.y;
    __stcs(&out[(size_t)warp * 32 + lane], acc);
}

// ---------------- tensor-core GEMM (bf16 split, 3-pass compensated) --------
__device__ __forceinline__ uint32_t smem_u32p(const void* p) {
    return (uint32_t)__cvta_generic_to_shared(p);
}

__device__ __forceinline__ void ldsm_x4(uint32_t* r, uint32_t addr) {
    asm volatile("ldmatrix.sync.aligned.m8n8.x4.shared.b16 {%0,%1,%2,%3}, [%4];"
                 : "=r"(r[0]), "=r"(r[1]), "=r"(r[2]), "=r"(r[3]) : "r"(addr));
}
__device__ __forceinline__ void ldsm_x2t(uint32_t* r, uint32_t addr) {
    asm volatile("ldmatrix.sync.aligned.m8n8.x2.trans.shared.b16 {%0,%1}, [%2];"
                 : "=r"(r[0]), "=r"(r[1]) : "r"(addr));
}
__device__ __forceinline__ void mma_bf16(float* c, const uint32_t* a, const uint32_t* b) {
    asm volatile(
        "mma.sync.aligned.m16n8k16.row.col.f32.bf16.bf16.f32 "
        "{%0,%1,%2,%3}, {%4,%5,%6,%7}, {%8,%9}, {%0,%1,%2,%3};"
        : "+f"(c[0]), "+f"(c[1]), "+f"(c[2]), "+f"(c[3])
        : "r"(a[0]), "r"(a[1]), "r"(a[2]), "r"(a[3]), "r"(b[0]), "r"(b[1]));
}

__device__ __forceinline__ void loadA4(const float* p, float* f) {
    float4 v = __ldcs((const float4*)p);
    f[0] = v.x; f[1] = v.y; f[2] = v.z; f[3] = v.w;
}
__device__ __forceinline__ void loadA4(const __half* p, float* f) {
    uint2 u = __ldcs((const uint2*)p);
    float2 a = __half22float2(*(const __half2*)&u.x);
    float2 b = __half22float2(*(const __half2*)&u.y);
    f[0] = a.x; f[1] = a.y; f[2] = b.x; f[3] = b.y;
}

template <int BN, typename TIn, bool PDL>
__global__ void __launch_bounds__(256)
k_gemm_tc(const TIn* __restrict__ A,
          const __nv_bfloat16* __restrict__ Wh,
          const __nv_bfloat16* __restrict__ Wl,
          __half* __restrict__ C) {
    constexpr int K   = 128;
    constexpr int BM  = 128;
    constexpr int BK  = 32;
    constexpr int BKP = 40;
    constexpr int BNP = BN + 8;
    constexpr int WNT = BN / 2;
    constexpr int NT  = WNT / 8;
    constexpr int MT  = 2;

    __shared__ __align__(16) __nv_bfloat16 sAh[BM][BKP];
    __shared__ __align__(16) __nv_bfloat16 sAl[BM][BKP];
    __shared__ __align__(16) __nv_bfloat16 sBh[BK][BNP];
    __shared__ __align__(16) __nv_bfloat16 sBl[BK][BNP];

    const int tid  = threadIdx.x;
    const int lane = tid & 31;
    const int wid  = tid >> 5;
    const int wm   = wid & 3;
    const int wn   = wid >> 2;
    const int m0   = blockIdx.x * BM;
    const int warp_m = wm * 32;
    const int warp_n = wn * WNT;

    // W-tile loader for chunk k0 (weights never depend on the producer)
    auto loadW = [&](int k0) {
        constexpr int PAIRS = BK * BN / 2;
        constexpr int PER   = PAIRS / 256;
#pragma unroll
        for (int i = 0; i < PER; i++) {
            int p  = tid + i * 256;
            int k  = p / (BN / 2);
            int n2 = p % (BN / 2);
            uint32_t vh = ((const uint32_t*)Wh)[(size_t)(k0 + k) * (BN / 2) + n2];
            uint32_t vl = ((const uint32_t*)Wl)[(size_t)(k0 + k) * (BN / 2) + n2];
            *(uint32_t*)&sBh[k][n2 * 2] = vh;
            *(uint32_t*)&sBl[k][n2 * 2] = vl;
        }
    };

    if (PDL) {
        loadW(0);                          // prologue overlaps producer tail
        cudaGridDependencySynchronize();   // wait: A (h1) complete
        cudaTriggerProgrammaticLaunchCompletion();
    }

    float c[MT][NT][4];
#pragma unroll
    for (int mt = 0; mt < MT; mt++)
#pragma unroll
        for (int nt = 0; nt < NT; nt++)
#pragma unroll
            for (int j = 0; j < 4; j++) c[mt][nt][j] = 0.0f;

    for (int k0 = 0; k0 < K; k0 += BK) {
        if (k0) __syncthreads();
        // ---- load + split A tile ----
        {
            const int r  = tid >> 3;
            const int c4 = tid & 7;
#pragma unroll
            for (int i = 0; i < 4; i++) {
                int row = r + i * 32;
                int m   = m0 + row;
                float f[4] = {0.f, 0.f, 0.f, 0.f};
                if (m < N_NODES)
                    loadA4(A + (size_t)m * K + k0 + c4 * 4, f);
#pragma unroll
                for (int j = 0; j < 4; j++) {
                    __nv_bfloat16 h = __float2bfloat16(f[j]);
                    sAh[row][c4 * 4 + j] = h;
                    sAl[row][c4 * 4 + j] = __float2bfloat16(f[j] - __bfloat162float(h));
                }
            }
        }
        if (!PDL || k0 > 0) loadW(k0);
        __syncthreads();

#pragma unroll
        for (int kc = 0; kc < BK; kc += 16) {
            uint32_t ah[MT][4], al[MT][4];
#pragma unroll
            for (int mt = 0; mt < MT; mt++) {
                int row = warp_m + mt * 16 + (lane & 15);
                int col = kc + (lane >> 4) * 8;
                ldsm_x4(ah[mt], smem_u32p(&sAh[row][col]));
                ldsm_x4(al[mt], smem_u32p(&sAl[row][col]));
            }
            int krow = kc + (lane & 7) + ((lane >> 3) & 1) * 8;
#pragma unroll
            for (int nt = 0; nt < NT; nt++) {
                int ncol = warp_n + nt * 8;
                uint32_t bh[2], bl[2];
                ldsm_x2t(bh, smem_u32p(&sBh[krow][ncol]));
                ldsm_x2t(bl, smem_u32p(&sBl[krow][ncol]));
#pragma unroll
                for (int mt = 0; mt < MT; mt++) {
                    mma_bf16(c[mt][nt], ah[mt], bh);
                    mma_bf16(c[mt][nt], al[mt], bh);
                    mma_bf16(c[mt][nt], ah[mt], bl);
                }
            }
        }
    }

    const int g = lane >> 2, t = lane & 3;
#pragma unroll
    for (int mt = 0; mt < MT; mt++) {
        int row0 = m0 + warp_m + mt * 16 + g;
        int row1 = row0 + 8;
#pragma unroll
        for (int nt = 0; nt < NT; nt++) {
            int col = warp_n + nt * 8 + t * 2;
            if (row0 < N_NODES)
                *(__half2*)(C + (size_t)row0 * BN + col) =
                    __floats2half2_rn(c[mt][nt][0], c[mt][nt][1]);
            if (row1 < N_NODES)
                *(__half2*)(C + (size_t)row1 * BN + col) =
                    __floats2half2_rn(c[mt][nt][2], c[mt][nt][3]);
        }
    }
}

// ---------------- launch ----------------
extern "C" void kernel_launch(void* const* d_in, const int* in_sizes, int n_in,
                              void* d_out, int out_size) {
    const float* feat = (const float*)d_in[0];
    const float* W1   = (const float*)d_in[1];
    const float* b1   = (const float*)d_in[2];
    const float* W2   = (const float*)d_in[3];
    const float* b2   = (const float*)d_in[4];
    const int*   src  = (const int*)d_in[5];
    const int*   dst  = (const int*)d_in[6];
    float*       out  = (float*)d_out;

    void *p_hn, *p_h1, *p_y2, *p_w1h, *p_w1l, *p_w2h, *p_w2l;
    cudaGetSymbolAddress(&p_hn, g_hn);
    cudaGetSymbolAddress(&p_h1, g_h1);
    cudaGetSymbolAddress(&p_y2, g_y2);
    cudaGetSymbolAddress(&p_w1h, g_W1h);
    cudaGetSymbolAddress(&p_w1l, g_W1l);
    cudaGetSymbolAddress(&p_w2h, g_W2h);
    cudaGetSymbolAddress(&p_w2l, g_W2l);
    __half* hn = (__half*)p_hn;   // F' = feat @ W1 (fp16)
    __half* h1 = (__half*)p_h1;
    __half* y2 = (__half*)p_y2;

    static cudaStream_t s_side = nullptr;
    static cudaEvent_t  e0 = nullptr, e1 = nullptr;
    static bool stream_ok = false;
    if (!s_side) {
        stream_ok =
            (cudaStreamCreateWithFlags(&s_side, cudaStreamNonBlocking) == cudaSuccess) &&
            (cudaEventCreateWithFlags(&e0, cudaEventDisableTiming) == cudaSuccess) &&
            (cudaEventCreateWithFlags(&e1, cudaEventDisableTiming) == cudaSuccess);
    }

    // init: zero counts + lookback flags + split weights
    k_init<<<(N_NODES + 255) / 256, 256>>>(
        W1, W2, (__nv_bfloat16*)p_w1h, (__nv_bfloat16*)p_w1l,
        (__nv_bfloat16*)p_w2h, (__nv_bfloat16*)p_w2l);

    if (stream_ok) {
        // fork: GEMM1 (feat @ W1 -> F' fp16) on side stream
        cudaEventRecord(e0, 0);
        cudaStreamWaitEvent(s_side, e0, 0);
        k_gemm_tc<128, float, false><<<(N_NODES + 127) / 128, 256, 0, s_side>>>(
            feat, (__nv_bfloat16*)p_w1h, (__nv_bfloat16*)p_w1l, hn);
        cudaEventRecord(e1, s_side);
    }

    // CSR build on main stream
    k_hist<<<(N_EDGES / 4 + 255) / 256, 256>>>((const int4*)dst);
    k_scan<<<SCAN_G, SCAN_B>>>();
    k_fill<<<(N_EDGES / 4 + 255) / 256, 256>>>((const int4*)src, (const int4*)dst);

    if (stream_ok) {
        cudaStreamWaitEvent(0, e1, 0);   // join: F' ready
    } else {
        k_gemm_tc<128, float, false><<<(N_NODES + 127) / 128, 256>>>(
            feat, (__nv_bfloat16*)p_w1h, (__nv_bfloat16*)p_w1l, hn);
    }

    // PDL launch config helper state
    cudaLaunchAttribute pdl_attr[1];
    pdl_attr[0].id = cudaLaunchAttributeProgrammaticStreamSerialization;
    pdl_attr[0].val.programmaticStreamSerializationAllowed = 1;

    // h1 = relu((agg(F') + F') * inv + b1)   — PDL over fill's tail
    {
        cudaLaunchConfig_t cfg{};
        cfg.gridDim  = dim3((N_NODES * 32 + 255) / 256);
        cfg.blockDim = dim3(256);
        cfg.stream   = 0;
        cfg.attrs = pdl_attr; cfg.numAttrs = 1;
        cudaLaunchKernelEx(&cfg, k_agg128h, (const uint2*)hn, (const float*)b1, (uint2*)h1);
    }
    // y2 = h1 @ W2   — PDL over agg128's tail (W-tile prologue)
    {
        cudaLaunchConfig_t cfg{};
        cfg.gridDim  = dim3((N_NODES + 127) / 128);
        cfg.blockDim = dim3(256);
        cfg.stream   = 0;
        cfg.attrs = pdl_attr; cfg.numAttrs = 1;
        cudaLaunchKernelEx(&cfg, k_gemm_tc<64, __half, true>,
                           (const __half*)h1,
                           (const __nv_bfloat16*)p_w2h, (const __nv_bfloat16*)p_w2l,
                           (__half*)y2);
    }
    // out = (agg(y2) + y2) * inv + b2   — PDL over gemm2's tail
    {
        cudaLaunchConfig_t cfg{};
        cfg.gridDim  = dim3((N_NODES * 32 + 255) / 256);
        cfg.blockDim = dim3(256);
        cfg.stream   = 0;
        cfg.attrs = pdl_attr; cfg.numAttrs = 1;
        cudaLaunchKernelEx(&cfg, k_agg64h, (const uint32_t*)y2, (const float*)b2, (float2*)out);
    }
}

// round 11
// speedup vs baseline: 1.3828x; 1.3828x over previous
#include <cuda_runtime.h>
#include <cuda_bf16.h>
#include <cuda_fp16.h>
#include <cstdint>

#define N_NODES 100000
#define N_EDGES 1600000
// dims: IN=128, HIDDEN=128, OUT=64

#define SCAN_B 1024
#define SCAN_G ((N_NODES + SCAN_B - 1) / SCAN_B)   // 98

// ---------------- scratch (device globals: allocation-free) ----------------
__device__ int    g_cnt[N_NODES];
__device__ int    g_off[N_NODES];
__device__ int    g_pos[N_NODES];
__device__ float  g_inv[N_NODES];
__device__ unsigned long long g_lk[SCAN_G];   // decoupled-lookback state
__device__ int    g_csr[N_EDGES];
__device__ __half g_hn [N_NODES * 128];   // F' = feat @ W1            (fp16)
__device__ __half g_h1 [N_NODES * 128];   // relu((agg+self)*inv + b1) (fp16)
__device__ __half g_y2 [N_NODES * 64];    // h1 @ W2                   (fp16)
__device__ __nv_bfloat16 g_W1h[128 * 128];
__device__ __nv_bfloat16 g_W1l[128 * 128];
__device__ __nv_bfloat16 g_W2h[128 * 64];
__device__ __nv_bfloat16 g_W2l[128 * 64];

// ---------------- init: zero counts + lookback state + split weights -------
__global__ void k_init(const float* __restrict__ W1,
                       const float* __restrict__ W2,
                       __nv_bfloat16* __restrict__ W1h,
                       __nv_bfloat16* __restrict__ W1l,
                       __nv_bfloat16* __restrict__ W2h,
                       __nv_bfloat16* __restrict__ W2l) {
    int i = blockIdx.x * blockDim.x + threadIdx.x;
    if (i < N_NODES) g_cnt[i] = 0;
    if (i < SCAN_G)  g_lk[i] = 0ull;
    if (i < 128 * 128) {
        float w = W1[i];
        __nv_bfloat16 h = __float2bfloat16(w);
        W1h[i] = h;
        W1l[i] = __float2bfloat16(w - __bfloat162float(h));
    }
    if (i < 128 * 64) {
        float w = W2[i];
        __nv_bfloat16 h = __float2bfloat16(w);
        W2h[i] = h;
        W2l[i] = __float2bfloat16(w - __bfloat162float(h));
    }
}

// ---------------- histogram (4 edges per thread, int4 loads) ----------------
__global__ void k_hist(const int4* __restrict__ dst4) {
    int t = blockIdx.x * blockDim.x + threadIdx.x;
    if (t < N_EDGES / 4) {
        int4 d = dst4[t];
        atomicAdd(&g_cnt[d.x], 1);
        atomicAdd(&g_cnt[d.y], 1);
        atomicAdd(&g_cnt[d.z], 1);
        atomicAdd(&g_cnt[d.w], 1);
    }
}

// ---------------- single-pass scan (decoupled lookback) --------------------
// 98 blocks, all resident simultaneously (98 < 148 SMs) -> spin-wait is safe.
__global__ void __launch_bounds__(SCAN_B)
k_scan() {
    __shared__ int sw[32];
    __shared__ int s_pref;
    const int t = threadIdx.x;
    const int b = blockIdx.x;
    const int i = b * SCAN_B + t;

    int v = (i < N_NODES) ? g_cnt[i] : 0;

    // warp-level inclusive scan
    int incl = v;
#pragma unroll
    for (int o = 1; o < 32; o <<= 1) {
        int y = __shfl_up_sync(0xffffffffu, incl, o);
        if ((t & 31) >= o) incl += y;
    }
    if ((t & 31) == 31) sw[t >> 5] = incl;
    __syncthreads();

    if (t < 32) {
        int x = sw[t];
        int xi = x;
#pragma unroll
        for (int o = 1; o < 32; o <<= 1) {
            int y = __shfl_up_sync(0xffffffffu, xi, o);
            if (t >= o) xi += y;
        }
        sw[t] = xi - x;                                   // exclusive warp offsets
        int total = __shfl_sync(0xffffffffu, xi, 31);     // block aggregate

        int pref = 0;
        if (b > 0) {
            if (t == 0)
                atomicExch(&g_lk[b], (1ull << 32) | (unsigned)total);
            int j = b - 1;
            while (true) {
                int jj = j - t;
                unsigned long long u;
                if (jj >= 0) {
                    do { u = *(volatile unsigned long long*)&g_lk[jj]; }
                    while ((u >> 32) == 0ull);
                } else {
                    u = (2ull << 32);   // virtual inclusive 0 below index 0
                }
                int flag = (int)(u >> 32);
                int val  = (int)(u & 0xffffffffu);
                unsigned mask = __ballot_sync(0xffffffffu, flag == 2);
                int k = __ffs(mask) - 1;
                int contrib;
                if (mask) contrib = (t <= k) ? val : 0;
                else      contrib = val;
#pragma unroll
                for (int o = 16; o > 0; o >>= 1)
                    contrib += __shfl_down_sync(0xffffffffu, contrib, o);
                contrib = __shfl_sync(0xffffffffu, contrib, 0);
                pref += contrib;
                if (mask) break;
                j -= 32;
            }
        }
        if (t == 0) {
            atomicExch(&g_lk[b], (2ull << 32) | (unsigned)(pref + total));
            s_pref = pref;
        }
    }
    __syncthreads();

    if (i < N_NODES) {
        int excl = incl - v + sw[t >> 5] + s_pref;
        g_off[i] = excl;
        g_pos[i] = excl;
        g_inv[i] = 1.0f / (float)(v + 1);
    }
}

// ---------------- CSR fill (4 edges per thread, int4 loads) ----------------
__global__ void k_fill(const int4* __restrict__ src4, const int4* __restrict__ dst4) {
    int t = blockIdx.x * blockDim.x + threadIdx.x;
    if (t < N_EDGES / 4) {
        int4 s = src4[t];
        int4 d = dst4[t];
        g_csr[atomicAdd(&g_pos[d.x], 1)] = s.x;
        g_csr[atomicAdd(&g_pos[d.y], 1)] = s.y;
        g_csr[atomicAdd(&g_pos[d.z], 1)] = s.z;
        g_csr[atomicAdd(&g_pos[d.w], 1)] = s.w;
    }
}

// ---------------- agg128 (fp16 in/out): h1 = relu((agg(F')+F')*inv + b1) ---
__global__ void __launch_bounds__(256)
k_agg128h(const uint2* __restrict__ x, const float* __restrict__ bias,
          uint2* __restrict__ out) {
    const int warp = (blockIdx.x * blockDim.x + threadIdx.x) >> 5;
    const int lane = threadIdx.x & 31;
    if (warp >= N_NODES) return;

    const int start = g_off[warp];
    const int cnt   = g_cnt[warp];

    float4 acc;
    {
        uint2 raw = x[(size_t)warp * 32 + lane];   // self term
        float2 a = __half22float2(*(const __half2*)&raw.x);
        float2 b = __half22float2(*(const __half2*)&raw.y);
        acc = make_float4(a.x, a.y, b.x, b.y);
    }

    for (int i0 = 0; i0 < cnt; i0 += 32) {
        const int nb = min(32, cnt - i0);
        int idx = 0;
        if (lane < nb) idx = g_csr[start + i0 + lane];

        int j = 0;
        for (; j + 8 <= nb; j += 8) {
            int s[8];
#pragma unroll
            for (int k = 0; k < 8; k++) s[k] = __shfl_sync(0xffffffffu, idx, j + k);
            uint2 v[8];
#pragma unroll
            for (int k = 0; k < 8; k++) v[k] = x[(size_t)s[k] * 32 + lane];
#pragma unroll
            for (int k = 0; k < 8; k++) {
                float2 a = __half22float2(*(const __half2*)&v[k].x);
                float2 b = __half22float2(*(const __half2*)&v[k].y);
                acc.x += a.x; acc.y += a.y; acc.z += b.x; acc.w += b.y;
            }
        }
        for (; j < nb; j++) {
            int s = __shfl_sync(0xffffffffu, idx, j);
            uint2 v = x[(size_t)s * 32 + lane];
            float2 a = __half22float2(*(const __half2*)&v.x);
            float2 b = __half22float2(*(const __half2*)&v.y);
            acc.x += a.x; acc.y += a.y; acc.z += b.x; acc.w += b.y;
        }
    }

    const float inv = g_inv[warp];
    float4 bb = ((const float4*)bias)[lane];
    acc.x = fmaxf(acc.x * inv + bb.x, 0.f);
    acc.y = fmaxf(acc.y * inv + bb.y, 0.f);
    acc.z = fmaxf(acc.z * inv + bb.z, 0.f);
    acc.w = fmaxf(acc.w * inv + bb.w, 0.f);
    uint2 o;
    *(__half2*)&o.x = __floats2half2_rn(acc.x, acc.y);
    *(__half2*)&o.y = __floats2half2_rn(acc.z, acc.w);
    __stcs(&out[(size_t)warp * 32 + lane], o);
}

// ---------------- agg64 (fp16 in, fp32 out): out = (agg(y2)+y2)*inv + b2 ---
__global__ void __launch_bounds__(256)
k_agg64h(const uint32_t* __restrict__ x, const float* __restrict__ bias,
         float2* __restrict__ out) {
    const int warp = (blockIdx.x * blockDim.x + threadIdx.x) >> 5;
    const int lane = threadIdx.x & 31;
    if (warp >= N_NODES) return;

    const int start = g_off[warp];
    const int cnt   = g_cnt[warp];

    float2 acc;
    {
        uint32_t raw = x[(size_t)warp * 32 + lane];   // self term
        acc = __half22float2(*(const __half2*)&raw);
    }

    for (int i0 = 0; i0 < cnt; i0 += 32) {
        const int nb = min(32, cnt - i0);
        int idx = 0;
        if (lane < nb) idx = g_csr[start + i0 + lane];

        int j = 0;
        for (; j + 8 <= nb; j += 8) {
            int s[8];
#pragma unroll
            for (int k = 0; k < 8; k++) s[k] = __shfl_sync(0xffffffffu, idx, j + k);
            uint32_t v[8];
#pragma unroll
            for (int k = 0; k < 8; k++) v[k] = x[(size_t)s[k] * 32 + lane];
#pragma unroll
            for (int k = 0; k < 8; k++) {
                float2 f = __half22float2(*(const __half2*)&v[k]);
                acc.x += f.x; acc.y += f.y;
            }
        }
        for (; j < nb; j++) {
            int s = __shfl_sync(0xffffffffu, idx, j);
            uint32_t v = x[(size_t)s * 32 + lane];
            float2 f = __half22float2(*(const __half2*)&v);
            acc.x += f.x; acc.y += f.y;
        }
    }

    const float inv = g_inv[warp];
    float2 bb = ((const float2*)bias)[lane];
    acc.x = acc.x * inv + bb.x;
    acc.y = acc.y * inv + bb.y;
    __stcs(&out[(size_t)warp * 32 + lane], acc);
}

// ---------------- tensor-core GEMM (bf16 split, 3-pass compensated) --------
__device__ __forceinline__ uint32_t smem_u32p(const void* p) {
    return (uint32_t)__cvta_generic_to_shared(p);
}

__device__ __forceinline__ void ldsm_x4(uint32_t* r, uint32_t addr) {
    asm volatile("ldmatrix.sync.aligned.m8n8.x4.shared.b16 {%0,%1,%2,%3}, [%4];"
                 : "=r"(r[0]), "=r"(r[1]), "=r"(r[2]), "=r"(r[3]) : "r"(addr));
}
__device__ __forceinline__ void ldsm_x2t(uint32_t* r, uint32_t addr) {
    asm volatile("ldmatrix.sync.aligned.m8n8.x2.trans.shared.b16 {%0,%1}, [%2];"
                 : "=r"(r[0]), "=r"(r[1]) : "r"(addr));
}
__device__ __forceinline__ void mma_bf16(float* c, const uint32_t* a, const uint32_t* b) {
    asm volatile(
        "mma.sync.aligned.m16n8k16.row.col.f32.bf16.bf16.f32 "
        "{%0,%1,%2,%3}, {%4,%5,%6,%7}, {%8,%9}, {%0,%1,%2,%3};"
        : "+f"(c[0]), "+f"(c[1]), "+f"(c[2]), "+f"(c[3])
        : "r"(a[0]), "r"(a[1]), "r"(a[2]), "r"(a[3]), "r"(b[0]), "r"(b[1]));
}

__device__ __forceinline__ void loadA4(const float* p, float* f) {
    float4 v = __ldcs((const float4*)p);
    f[0] = v.x; f[1] = v.y; f[2] = v.z; f[3] = v.w;
}
__device__ __forceinline__ void loadA4(const __half* p, float* f) {
    uint2 u = __ldcs((const uint2*)p);
    float2 a = __half22float2(*(const __half2*)&u.x);
    float2 b = __half22float2(*(const __half2*)&u.y);
    f[0] = a.x; f[1] = a.y; f[2] = b.x; f[3] = b.y;
}

template <int BN, typename TIn>
__global__ void __launch_bounds__(256)
k_gemm_tc(const TIn* __restrict__ A,
          const __nv_bfloat16* __restrict__ Wh,
          const __nv_bfloat16* __restrict__ Wl,
          __half* __restrict__ C) {
    constexpr int K   = 128;
    constexpr int BM  = 128;
    constexpr int BK  = 32;
    constexpr int BKP = 40;
    constexpr int BNP = BN + 8;
    constexpr int WNT = BN / 2;
    constexpr int NT  = WNT / 8;
    constexpr int MT  = 2;

    __shared__ __align__(16) __nv_bfloat16 sAh[BM][BKP];
    __shared__ __align__(16) __nv_bfloat16 sAl[BM][BKP];
    __shared__ __align__(16) __nv_bfloat16 sBh[BK][BNP];
    __shared__ __align__(16) __nv_bfloat16 sBl[BK][BNP];

    const int tid  = threadIdx.x;
    const int lane = tid & 31;
    const int wid  = tid >> 5;
    const int wm   = wid & 3;
    const int wn   = wid >> 2;
    const int m0   = blockIdx.x * BM;
    const int warp_m = wm * 32;
    const int warp_n = wn * WNT;

    float c[MT][NT][4];
#pragma unroll
    for (int mt = 0; mt < MT; mt++)
#pragma unroll
        for (int nt = 0; nt < NT; nt++)
#pragma unroll
            for (int j = 0; j < 4; j++) c[mt][nt][j] = 0.0f;

    for (int k0 = 0; k0 < K; k0 += BK) {
        if (k0) __syncthreads();
        // ---- load + split A tile ----
        {
            const int r  = tid >> 3;
            const int c4 = tid & 7;
#pragma unroll
            for (int i = 0; i < 4; i++) {
                int row = r + i * 32;
                int m   = m0 + row;
                float f[4] = {0.f, 0.f, 0.f, 0.f};
                if (m < N_NODES)
                    loadA4(A + (size_t)m * K + k0 + c4 * 4, f);
#pragma unroll
                for (int j = 0; j < 4; j++) {
                    __nv_bfloat16 h = __float2bfloat16(f[j]);
                    sAh[row][c4 * 4 + j] = h;
                    sAl[row][c4 * 4 + j] = __float2bfloat16(f[j] - __bfloat162float(h));
                }
            }
        }
        // ---- load W tile (pre-split bf16, row-major [K][BN]) ----
        {
            constexpr int PAIRS = BK * BN / 2;
            constexpr int PER   = PAIRS / 256;
#pragma unroll
            for (int i = 0; i < PER; i++) {
                int p  = tid + i * 256;
                int k  = p / (BN / 2);
                int n2 = p % (BN / 2);
                uint32_t vh = ((const uint32_t*)Wh)[(size_t)(k0 + k) * (BN / 2) + n2];
                uint32_t vl = ((const uint32_t*)Wl)[(size_t)(k0 + k) * (BN / 2) + n2];
                *(uint32_t*)&sBh[k][n2 * 2] = vh;
                *(uint32_t*)&sBl[k][n2 * 2] = vl;
            }
        }
        __syncthreads();

#pragma unroll
        for (int kc = 0; kc < BK; kc += 16) {
            uint32_t ah[MT][4], al[MT][4];
#pragma unroll
            for (int mt = 0; mt < MT; mt++) {
                int row = warp_m + mt * 16 + (lane & 15);
                int col = kc + (lane >> 4) * 8;
                ldsm_x4(ah[mt], smem_u32p(&sAh[row][col]));
                ldsm_x4(al[mt], smem_u32p(&sAl[row][col]));
            }
            int krow = kc + (lane & 7) + ((lane >> 3) & 1) * 8;
#pragma unroll
            for (int nt = 0; nt < NT; nt++) {
                int ncol = warp_n + nt * 8;
                uint32_t bh[2], bl[2];
                ldsm_x2t(bh, smem_u32p(&sBh[krow][ncol]));
                ldsm_x2t(bl, smem_u32p(&sBl[krow][ncol]));
#pragma unroll
                for (int mt = 0; mt < MT; mt++) {
                    mma_bf16(c[mt][nt], ah[mt], bh);
                    mma_bf16(c[mt][nt], al[mt], bh);
                    mma_bf16(c[mt][nt], ah[mt], bl);
                }
            }
        }
    }

    const int g = lane >> 2, t = lane & 3;
#pragma unroll
    for (int mt = 0; mt < MT; mt++) {
        int row0 = m0 + warp_m + mt * 16 + g;
        int row1 = row0 + 8;
#pragma unroll
        for (int nt = 0; nt < NT; nt++) {
            int col = warp_n + nt * 8 + t * 2;
            if (row0 < N_NODES)
                *(__half2*)(C + (size_t)row0 * BN + col) =
                    __floats2half2_rn(c[mt][nt][0], c[mt][nt][1]);
            if (row1 < N_NODES)
                *(__half2*)(C + (size_t)row1 * BN + col) =
                    __floats2half2_rn(c[mt][nt][2], c[mt][nt][3]);
        }
    }
}

// ---------------- launch ----------------
extern "C" void kernel_launch(void* const* d_in, const int* in_sizes, int n_in,
                              void* d_out, int out_size) {
    const float* feat = (const float*)d_in[0];
    const float* W1   = (const float*)d_in[1];
    const float* b1   = (const float*)d_in[2];
    const float* W2   = (const float*)d_in[3];
    const float* b2   = (const float*)d_in[4];
    const int*   src  = (const int*)d_in[5];
    const int*   dst  = (const int*)d_in[6];
    float*       out  = (float*)d_out;

    void *p_hn, *p_h1, *p_y2, *p_w1h, *p_w1l, *p_w2h, *p_w2l;
    cudaGetSymbolAddress(&p_hn, g_hn);
    cudaGetSymbolAddress(&p_h1, g_h1);
    cudaGetSymbolAddress(&p_y2, g_y2);
    cudaGetSymbolAddress(&p_w1h, g_W1h);
    cudaGetSymbolAddress(&p_w1l, g_W1l);
    cudaGetSymbolAddress(&p_w2h, g_W2h);
    cudaGetSymbolAddress(&p_w2l, g_W2l);
    __half* hn = (__half*)p_hn;   // F' = feat @ W1 (fp16)
    __half* h1 = (__half*)p_h1;
    __half* y2 = (__half*)p_y2;

    static cudaStream_t s_side = nullptr;
    static cudaEvent_t  e0 = nullptr, e1 = nullptr;
    static bool stream_ok = false;
    if (!s_side) {
        stream_ok =
            (cudaStreamCreateWithFlags(&s_side, cudaStreamNonBlocking) == cudaSuccess) &&
            (cudaEventCreateWithFlags(&e0, cudaEventDisableTiming) == cudaSuccess) &&
            (cudaEventCreateWithFlags(&e1, cudaEventDisableTiming) == cudaSuccess);
    }

    // init: zero counts + lookback flags + split weights
    k_init<<<(N_NODES + 255) / 256, 256>>>(
        W1, W2, (__nv_bfloat16*)p_w1h, (__nv_bfloat16*)p_w1l,
        (__nv_bfloat16*)p_w2h, (__nv_bfloat16*)p_w2l);

    if (stream_ok) {
        // fork: GEMM1 (feat @ W1 -> F' fp16) on side stream, CSR build on main
        cudaEventRecord(e0, 0);
        cudaStreamWaitEvent(s_side, e0, 0);
        k_gemm_tc<128, float><<<(N_NODES + 127) / 128, 256, 0, s_side>>>(
            feat, (__nv_bfloat16*)p_w1h, (__nv_bfloat16*)p_w1l, hn);
        cudaEventRecord(e1, s_side);
    }

    // CSR build on main stream
    k_hist<<<(N_EDGES / 4 + 255) / 256, 256>>>((const int4*)dst);
    k_scan<<<SCAN_G, SCAN_B>>>();
    k_fill<<<(N_EDGES / 4 + 255) / 256, 256>>>((const int4*)src, (const int4*)dst);

    if (stream_ok) {
        cudaStreamWaitEvent(0, e1, 0);   // join: F' ready
    } else {
        k_gemm_tc<128, float><<<(N_NODES + 127) / 128, 256>>>(
            feat, (__nv_bfloat16*)p_w1h, (__nv_bfloat16*)p_w1l, hn);
    }

    // h1 = relu((agg(F') + F') * inv + b1)   (fp16 gather)
    k_agg128h<<<(N_NODES * 32 + 255) / 256, 256>>>((const uint2*)hn, b1, (uint2*)h1);
    // y2 = h1 @ W2   (fp16 in/out)
    k_gemm_tc<64, __half><<<(N_NODES + 127) / 128, 256>>>(
        h1, (__nv_bfloat16*)p_w2h, (__nv_bfloat16*)p_w2l, y2);
    // out = (agg(y2) + y2) * inv + b2   (fp16 gather, fp32 out)
    k_agg64h<<<(N_NODES * 32 + 255) / 256, 256>>>((const uint32_t*)y2, b2, (float2*)out);
}